// round 16
// baseline (speedup 1.0000x reference)
#include <cuda_runtime.h>
#include <cuda_fp16.h>
#include <math.h>
#include <stdint.h>

// ---------------- problem constants ----------------
constexpr int B_  = 512;
constexpr int T_  = 200;
constexpr int D_  = 64;
constexpr int H_  = 256;
constexpr int BT  = B_ * T_;        // 102400 rows
constexpr int HT  = H_ * T_;        // 51200 flat dim
constexpr int C1_ = 1024;
constexpr int C2_ = 256;
constexpr int C3_ = 10;
constexpr int R1_ = 1024;
constexpr int G3  = 768;            // packed gates i,g,o (forget gate dead, c0=0)

constexpr size_t OUT_TOTAL_OFF = 0;
constexpr size_t OUT_CLASS_OFF = (size_t)BT * H_;
constexpr size_t OUT_REG_OFF   = OUT_CLASS_OFF + (size_t)B_ * C3_;

// ---------------- device scratch ----------------
__device__ __half g_w0h[G3 * D_];           // packed i,g,o rows fp16
__device__ __half g_w1h[G3 * H_];
__device__ float  g_bsel0[G3], g_bsel1[G3];
__device__ __half g_xh [(size_t)BT * D_];   // fp16 input
__device__ __half g_h0h[(size_t)BT * H_];   // fp16 h0
__device__ __half g_fh [(size_t)BT * H_];   // fp16 flat (out_total)
__device__ __half g_f1h[(size_t)C1_ * HT];  // fp16 fc1 weights
__device__ __half g_f4h[(size_t)R1_ * HT];  // fp16 fc4 weights
__device__ float  g_part[16 * 512 * 1024];  // split-K partials
__device__ float  g_c1[B_ * C1_];
__device__ float  g_c2[B_ * C2_];
__device__ float  g_r [B_ * R1_];

// ---------------- PTX helpers (sm_80-compatible only) ----------------
__device__ __forceinline__ uint32_t smem_u32(const void* p) {
    uint32_t a;
    asm("{ .reg .u64 t; cvta.to.shared.u64 t, %1; cvt.u32.u64 %0, t; }" : "=r"(a) : "l"(p));
    return a;
}
__device__ __forceinline__ void cp_async16(uint32_t dst, const void* src) {
    asm volatile("cp.async.cg.shared.global [%0], [%1], 16;" :: "r"(dst), "l"(src));
}
#define CP_COMMIT() asm volatile("cp.async.commit_group;" ::: "memory")
template <int N>
__device__ __forceinline__ void cp_wait() {
    asm volatile("cp.async.wait_group %0;" :: "n"(N) : "memory");
}
__device__ __forceinline__ void ldsm_x4(uint32_t* r, uint32_t addr) {
    asm volatile("ldmatrix.sync.aligned.m8n8.x4.shared.b16 {%0,%1,%2,%3}, [%4];"
                 : "=r"(r[0]), "=r"(r[1]), "=r"(r[2]), "=r"(r[3]) : "r"(addr));
}
__device__ __forceinline__ void mma_f16(float* c, const uint32_t* a, const uint32_t* b) {
    asm volatile("mma.sync.aligned.m16n8k16.row.col.f32.f16.f16.f32 "
                 "{%0,%1,%2,%3}, {%4,%5,%6,%7}, {%8,%9}, {%0,%1,%2,%3};"
                 : "+f"(c[0]), "+f"(c[1]), "+f"(c[2]), "+f"(c[3])
                 : "r"(a[0]), "r"(a[1]), "r"(a[2]), "r"(a[3]), "r"(b[0]), "r"(b[1]));
}
__device__ __forceinline__ uint32_t pack_h2(float a, float b) {
    __half2 t = __floats2half2_rn(a, b);
    return *reinterpret_cast<uint32_t*>(&t);
}
__device__ __forceinline__ float sigm(float x) { return 1.f / (1.f + expf(-x)); }

constexpr int HS_ROWB  = 144;               // 64 fp16 + 8 pad, bytes
constexpr int HS_TILE  = 128 * HS_ROWB;     // 18432
constexpr int HS_STAGE = 2 * HS_TILE;       // 36864 (A | B)  — fc kernel
constexpr int HS_SMEM  = 3 * HS_STAGE;      // 110592         — fc kernel

// gate kernel: stage = A | B_i | B_g | B_o, double buffered
constexpr int G3_STAGE = 4 * HS_TILE;       // 73728
constexpr int G3_SMEM  = 2 * G3_STAGE;      // 147456

// ---------------- fused 3-gate fp16 GEMM (LSTM layers) ----------------
// ONE pass over K: acc_g = A * Wsel[g*256+n,:]^T for g in {i,g,o} simultaneously.
// h = sigm(o+b) * tanh( sigm(i+b) * tanh(g+b) ) computed directly from accs.
// Tile 128x128x64, 512 threads, warp grid 4x4, warp tile 32x32, 2-stage cp.async.
__global__ void __launch_bounds__(512, 1)
hs_gate3(const __half* __restrict__ A, const __half* __restrict__ Bw,
         float* __restrict__ C, const float* __restrict__ bias,
         __half* __restrict__ outH, int M, int K)
{
    extern __shared__ __align__(128) char smem[];
    const uint32_t sBase = smem_u32(smem);

    const int tid  = threadIdx.x;
    const int lane = tid & 31;
    const int warp = tid >> 5;
    const int wm   = warp >> 2;              // 0..3
    const int wn   = warp & 3;               // 0..3
    const int mBase = blockIdx.y * 128;
    const int nBase = blockIdx.x * 128;      // within H=256
    const int NC    = K >> 6;

    const int aRow  = (lane & 7) + ((lane >> 3) & 1) * 8;
    const int aCol  = (lane >> 4) * 8;
    const int bRow4 = ((lane >> 4) & 1) * 8 + (lane & 7);
    const int bColH = ((lane >> 3) & 1) * 8;

    const int lrow0 = tid >> 3;              // 0..63
    const int lrow1 = lrow0 + 64;
    const int lc8   = tid & 7;

    float acc[3][2][4][4];
#pragma unroll
    for (int g = 0; g < 3; g++)
#pragma unroll
        for (int mi = 0; mi < 2; mi++)
#pragma unroll
            for (int ni = 0; ni < 4; ni++)
#pragma unroll
                for (int q = 0; q < 4; q++) acc[g][mi][ni][q] = 0.f;

    auto prefetch = [&](int c) {
        if (c < NC) {
            int kk = c * 64;
            uint32_t st = sBase + (c & 1) * G3_STAGE;
            cp_async16(st + lrow0 * HS_ROWB + lc8 * 16,
                       A + (size_t)(mBase + lrow0) * K + kk + lc8 * 8);
            cp_async16(st + lrow1 * HS_ROWB + lc8 * 16,
                       A + (size_t)(mBase + lrow1) * K + kk + lc8 * 8);
#pragma unroll
            for (int g = 0; g < 3; g++) {
                int rowOff = g * 256 + nBase;
                uint32_t bt = st + (g + 1) * HS_TILE;
                cp_async16(bt + lrow0 * HS_ROWB + lc8 * 16,
                           Bw + (size_t)(rowOff + lrow0) * K + kk + lc8 * 8);
                cp_async16(bt + lrow1 * HS_ROWB + lc8 * 16,
                           Bw + (size_t)(rowOff + lrow1) * K + kk + lc8 * 8);
            }
        }
        CP_COMMIT();                          // unconditional: fixed group count
    };

    prefetch(0); prefetch(1);

    for (int c = 0; c < NC; c++) {
        cp_wait<1>();                        // group c complete (2 in flight)
        __syncthreads();

        uint32_t sA = sBase + (c & 1) * G3_STAGE;
#pragma unroll
        for (int ks = 0; ks < 4; ks++) {
            uint32_t ah[2][4];
#pragma unroll
            for (int mi = 0; mi < 2; mi++) {
                uint32_t ro = (wm * 32 + mi * 16 + aRow) * HS_ROWB + (ks * 16 + aCol) * 2;
                ldsm_x4(ah[mi], sA + ro);
            }
#pragma unroll
            for (int g = 0; g < 3; g++) {
                uint32_t sB = sA + (g + 1) * HS_TILE;
                uint32_t bh[2][4];
#pragma unroll
                for (int p = 0; p < 2; p++) {
                    uint32_t ro = (wn * 32 + p * 16 + bRow4) * HS_ROWB + (ks * 16 + bColH) * 2;
                    ldsm_x4(bh[p], sB + ro);
                }
#pragma unroll
                for (int mi = 0; mi < 2; mi++)
#pragma unroll
                    for (int ni = 0; ni < 4; ni++)
                        mma_f16(acc[g][mi][ni], ah[mi], &bh[ni >> 1][(ni & 1) * 2]);
            }
        }
        __syncthreads();                     // stage drained before refill
        prefetch(c + 2);
    }

    // ---- epilogue: compose LSTM gate directly from the 3 accs ----
#pragma unroll
    for (int mi = 0; mi < 2; mi++)
#pragma unroll
        for (int ni = 0; ni < 4; ni++)
#pragma unroll
            for (int q = 0; q < 4; q++) {
                int rl = wm * 32 + mi * 16 + (lane >> 2) + ((q >= 2) ? 8 : 0);
                int cl = wn * 32 + ni * 8 + (lane & 3) * 2 + (q & 1);
                float vi = acc[0][mi][ni][q] + bias[nBase + cl];
                float vg = acc[1][mi][ni][q] + bias[256 + nBase + cl];
                float vo = acc[2][mi][ni][q] + bias[512 + nBase + cl];
                float h = sigm(vo) * tanhf(sigm(vi) * tanhf(vg));
                size_t o = (size_t)(mBase + rl) * H_ + nBase + cl;
                if (C) C[o] = h;
                outH[o] = __float2half(h);
            }
}

// ---------------- fc fp16 GEMM: 64x32 warp tile, 2 CTAs/SM (R13 validated) ----------------
__global__ void __launch_bounds__(256, 2)
hs_fc(const __half* __restrict__ A, const __half* __restrict__ Bw,
      float* __restrict__ C, int M, int N, int K, int kSlice)
{
    extern __shared__ __align__(128) char smem[];
    const uint32_t sBase = smem_u32(smem);

    const int tid  = threadIdx.x;
    const int lane = tid & 31;
    const int warp = tid >> 5;               // 0..7
    const int wm   = warp >> 2;              // 0..1 (64 M-rows each)
    const int wn   = warp & 3;               // 0..3 (32 N-cols each)
    const int mBase = blockIdx.y * 128;
    const int nBase = blockIdx.x * 128;
    const int z     = blockIdx.z;
    const int kBeg  = z * kSlice;
    const int NC    = kSlice >> 6;

    const int aRow  = (lane & 7) + ((lane >> 3) & 1) * 8;
    const int aCol  = (lane >> 4) * 8;
    const int bRow4 = ((lane >> 4) & 1) * 8 + (lane & 7);
    const int bColH = ((lane >> 3) & 1) * 8;

    const int lc8 = tid & 7;
    int lrw[4];
#pragma unroll
    for (int t = 0; t < 4; t++) lrw[t] = (tid + t * 256) >> 3;   // 0..127

    float acc[4][4][4];
#pragma unroll
    for (int mi = 0; mi < 4; mi++)
#pragma unroll
        for (int ni = 0; ni < 4; ni++)
#pragma unroll
            for (int q = 0; q < 4; q++) acc[mi][ni][q] = 0.f;

    auto prefetch = [&](int c) {
        if (c < NC) {
            int kk = kBeg + c * 64;
            uint32_t st = sBase + (c % 3) * HS_STAGE;
#pragma unroll
            for (int t = 0; t < 4; t++) {
                cp_async16(st + lrw[t] * HS_ROWB + lc8 * 16,
                           A + (size_t)(mBase + lrw[t]) * K + kk + lc8 * 8);
                cp_async16(st + HS_TILE + lrw[t] * HS_ROWB + lc8 * 16,
                           Bw + (size_t)(nBase + lrw[t]) * K + kk + lc8 * 8);
            }
        }
        CP_COMMIT();
    };

    prefetch(0); prefetch(1); prefetch(2);

    for (int c = 0; c < NC; c++) {
        cp_wait<2>();
        __syncthreads();

        uint32_t sA = sBase + (c % 3) * HS_STAGE;
        uint32_t sB = sA + HS_TILE;
#pragma unroll
        for (int ks = 0; ks < 4; ks++) {
            uint32_t ah[4][4], bh[2][4];
#pragma unroll
            for (int mi = 0; mi < 4; mi++) {
                uint32_t ro = (wm * 64 + mi * 16 + aRow) * HS_ROWB + (ks * 16 + aCol) * 2;
                ldsm_x4(ah[mi], sA + ro);
            }
#pragma unroll
            for (int p = 0; p < 2; p++) {
                uint32_t ro = (wn * 32 + p * 16 + bRow4) * HS_ROWB + (ks * 16 + bColH) * 2;
                ldsm_x4(bh[p], sB + ro);
            }
#pragma unroll
            for (int mi = 0; mi < 4; mi++)
#pragma unroll
                for (int ni = 0; ni < 4; ni++)
                    mma_f16(acc[mi][ni], ah[mi], &bh[ni >> 1][(ni & 1) * 2]);
        }
        __syncthreads();
        prefetch(c + 3);
    }

    float* Cp = C + (size_t)z * M * N;
#pragma unroll
    for (int mi = 0; mi < 4; mi++) {
        int r0 = mBase + wm * 64 + mi * 16 + (lane >> 2);
#pragma unroll
        for (int ni = 0; ni < 4; ni++) {
            int col = nBase + wn * 32 + ni * 8 + (lane & 3) * 2;
            *reinterpret_cast<float2*>(&Cp[(size_t)r0 * N + col]) =
                make_float2(acc[mi][ni][0], acc[mi][ni][1]);
            *reinterpret_cast<float2*>(&Cp[(size_t)(r0 + 8) * N + col]) =
                make_float2(acc[mi][ni][2], acc[mi][ni][3]);
        }
    }
}

// ---------------- prep kernels ----------------
__global__ void cvt_f16(const float4* __restrict__ src, uint2* __restrict__ dst, int n4)
{
    int i = blockIdx.x * blockDim.x + threadIdx.x;
    if (i >= n4) return;
    float4 v = src[i];
    dst[i] = make_uint2(pack_h2(v.x, v.y), pack_h2(v.z, v.w));
}

__global__ void make_wsel_f16(const float* __restrict__ W, const float* __restrict__ bih,
                              const float* __restrict__ bhh, __half* __restrict__ Wh,
                              float* __restrict__ bsel, int Kd)
{
    int idx = blockIdx.x * blockDim.x + threadIdx.x;
    int total = G3 * Kd;
    if (idx < total) {
        int j = idx / Kd;
        int c = idx - j * Kd;
        int src = j + ((j >= 256) ? 256 : 0);
        Wh[idx] = __float2half(W[src * Kd + c]);
    }
    if (idx < G3) {
        int src = idx + ((idx >= 256) ? 256 : 0);
        bsel[idx] = bih[src] + bhh[src];
    }
}

__global__ void reduce_bias_act(const float* __restrict__ part, int S, int MN, int N,
                                const float* __restrict__ bias, float* __restrict__ out, int relu)
{
    int idx = blockIdx.x * blockDim.x + threadIdx.x;
    if (idx >= MN) return;
    float s = 0.f;
    for (int i = 0; i < S; i++) s += part[(size_t)i * MN + idx];
    s += bias[idx % N];
    if (relu) s = fmaxf(s, 0.f);
    out[idx] = s;
}

// ---------------- fp32 SGEMM (small fc layers) ----------------
__global__ void __launch_bounds__(256, 2)
sgemm_nt(const float* __restrict__ A, const float* __restrict__ B,
         float* __restrict__ C, int M, int N, int K, int kSlice)
{
    constexpr int BM = 128, BN = 128, BK = 8;
    __shared__ float As[BK][BM];
    __shared__ float Bs[BK][BN];
    const int tid = threadIdx.x;
    const int mBase = blockIdx.y * BM;
    const int nBase = blockIdx.x * BN;
    const int z = blockIdx.z;
    const int kBeg = z * kSlice;
    const int kEnd = kBeg + kSlice;
    const int lr = tid >> 1;
    const int lc = (tid & 1) * 4;
    const int tr = (tid >> 4) * 8;
    const int tc = (tid & 15) * 8;
    float acc[8][8];
#pragma unroll
    for (int i = 0; i < 8; i++)
#pragma unroll
        for (int j = 0; j < 8; j++) acc[i][j] = 0.f;
    const float* Aptr = A + (size_t)(mBase + lr) * K;
    const bool bvalid = (nBase + lr) < N;
    const float* Bptr = B + (bvalid ? (size_t)(nBase + lr) * K : 0);
    for (int k0 = kBeg; k0 < kEnd; k0 += BK) {
        float4 a4 = *reinterpret_cast<const float4*>(Aptr + k0 + lc);
        float4 b4 = make_float4(0.f, 0.f, 0.f, 0.f);
        if (bvalid) b4 = *reinterpret_cast<const float4*>(Bptr + k0 + lc);
        As[lc + 0][lr] = a4.x; As[lc + 1][lr] = a4.y;
        As[lc + 2][lr] = a4.z; As[lc + 3][lr] = a4.w;
        Bs[lc + 0][lr] = b4.x; Bs[lc + 1][lr] = b4.y;
        Bs[lc + 2][lr] = b4.z; Bs[lc + 3][lr] = b4.w;
        __syncthreads();
#pragma unroll
        for (int kk = 0; kk < BK; kk++) {
            float rm[8], rn[8];
#pragma unroll
            for (int i = 0; i < 8; i++) rm[i] = As[kk][tr + i];
#pragma unroll
            for (int j = 0; j < 8; j++) rn[j] = Bs[kk][tc + j];
#pragma unroll
            for (int i = 0; i < 8; i++)
#pragma unroll
                for (int j = 0; j < 8; j++) acc[i][j] = fmaf(rm[i], rn[j], acc[i][j]);
        }
        __syncthreads();
    }
    float* Cp = C + (size_t)z * M * N;
#pragma unroll
    for (int i = 0; i < 8; i++) {
        const size_t rowOff = (size_t)(mBase + tr + i) * N;
#pragma unroll
        for (int j = 0; j < 8; j++) {
            int col = nBase + tc + j;
            if (col < N) Cp[rowOff + col] = acc[i][j];
        }
    }
}

__global__ void fc3_kernel(const float* __restrict__ x, const float* __restrict__ W,
                           const float* __restrict__ b, float* __restrict__ out)
{
    int idx = blockIdx.x * blockDim.x + threadIdx.x;
    if (idx >= B_ * C3_) return;
    int m = idx / C3_;
    int n = idx - m * C3_;
    const float* xr = x + m * C2_;
    const float* wr = W + n * C2_;
    float s = 0.f;
#pragma unroll 4
    for (int k = 0; k < C2_; k++) s = fmaf(xr[k], wr[k], s);
    out[idx] = s + b[n];
}

// ---------------- launch ----------------
extern "C" void kernel_launch(void* const* d_in, const int* in_sizes, int n_in,
                              void* d_out_v, int out_size)
{
    const float* x     = (const float*)d_in[0];
    const float* W_ih0 = (const float*)d_in[1];
    const float* b_ih0 = (const float*)d_in[2];
    const float* b_hh0 = (const float*)d_in[3];
    const float* W_ih1 = (const float*)d_in[4];
    const float* b_ih1 = (const float*)d_in[5];
    const float* b_hh1 = (const float*)d_in[6];
    const float* fc1_w = (const float*)d_in[7];
    const float* fc1_b = (const float*)d_in[8];
    const float* fc2_w = (const float*)d_in[9];
    const float* fc2_b = (const float*)d_in[10];
    const float* fc3_w = (const float*)d_in[11];
    const float* fc3_b = (const float*)d_in[12];
    const float* fc4_w = (const float*)d_in[13];
    const float* fc4_b = (const float*)d_in[14];
    const float* fc5_w = (const float*)d_in[15];
    const float* fc5_b = (const float*)d_in[16];
    float* d_out = (float*)d_out_v;

    cudaFuncSetAttribute(hs_gate3, cudaFuncAttributeMaxDynamicSharedMemorySize, G3_SMEM);
    cudaFuncSetAttribute(hs_fc,    cudaFuncAttributeMaxDynamicSharedMemorySize, HS_SMEM);

    __half *w0h, *w1h, *xh, *h0h, *fh, *f1h, *f4h;
    float *bsel0, *bsel1, *part, *c1, *c2, *r;
    cudaGetSymbolAddress((void**)&w0h, g_w0h);
    cudaGetSymbolAddress((void**)&w1h, g_w1h);
    cudaGetSymbolAddress((void**)&bsel0, g_bsel0);
    cudaGetSymbolAddress((void**)&bsel1, g_bsel1);
    cudaGetSymbolAddress((void**)&xh,  g_xh);
    cudaGetSymbolAddress((void**)&h0h, g_h0h);
    cudaGetSymbolAddress((void**)&fh,  g_fh);
    cudaGetSymbolAddress((void**)&f1h, g_f1h);
    cudaGetSymbolAddress((void**)&f4h, g_f4h);
    cudaGetSymbolAddress((void**)&part, g_part);
    cudaGetSymbolAddress((void**)&c1, g_c1);
    cudaGetSymbolAddress((void**)&c2, g_c2);
    cudaGetSymbolAddress((void**)&r,  g_r);

    // prep: pack gate weights fp16 + convert x / fc weights to fp16 (one-time)
    make_wsel_f16<<<(G3 * D_ + 255) / 256, 256>>>(W_ih0, b_ih0, b_hh0, w0h, bsel0, D_);
    make_wsel_f16<<<(G3 * H_ + 255) / 256, 256>>>(W_ih1, b_ih1, b_hh1, w1h, bsel1, H_);
    cvt_f16<<<(BT * D_ / 4 + 255) / 256, 256>>>((const float4*)x, (uint2*)xh, BT * D_ / 4);
    cvt_f16<<<(C1_ * HT / 4 + 255) / 256, 256>>>((const float4*)fc1_w, (uint2*)f1h, C1_ * HT / 4);
    cvt_f16<<<(R1_ * HT / 4 + 255) / 256, 256>>>((const float4*)fc4_w, (uint2*)f4h, R1_ * HT / 4);

    // LSTM layer 0 (fused 3-gate): h0 fp16 = lstm(x @ Wsel0^T + bsel0)
    hs_gate3<<<dim3(2, BT / 128, 1), 512, G3_SMEM>>>(
        xh, w0h, nullptr, bsel0, h0h, BT, D_);

    // LSTM layer 1 (fused 3-gate): out_total fp32 -> d_out, flat fp16 -> fh
    hs_gate3<<<dim3(2, BT / 128, 1), 512, G3_SMEM>>>(
        h0h, w1h, d_out + OUT_TOTAL_OFF, bsel1, fh, BT, H_);

    // fc1 (split-K=16) + relu
    hs_fc<<<dim3(C1_ / 128, B_ / 128, 16), 256, HS_SMEM>>>(
        fh, f1h, part, B_, C1_, HT, HT / 16);
    reduce_bias_act<<<(B_ * C1_ + 255) / 256, 256>>>(part, 16, B_ * C1_, C1_, fc1_b, c1, 1);

    // fc2 (fp32 path) + relu
    sgemm_nt<<<dim3(C2_ / 128, B_ / 128, 4), 256>>>(c1, fc2_w, part, B_, C2_, C1_, C1_ / 4);
    reduce_bias_act<<<(B_ * C2_ + 255) / 256, 256>>>(part, 4, B_ * C2_, C2_, fc2_b, c2, 1);

    // fc3 -> class output
    fc3_kernel<<<(B_ * C3_ + 255) / 256, 256>>>(c2, fc3_w, fc3_b, d_out + OUT_CLASS_OFF);

    // fc4 (split-K=16) + relu
    hs_fc<<<dim3(R1_ / 128, B_ / 128, 16), 256, HS_SMEM>>>(
        fh, f4h, part, B_, R1_, HT, HT / 16);
    reduce_bias_act<<<(B_ * R1_ + 255) / 256, 256>>>(part, 16, B_ * R1_, R1_, fc4_b, r, 1);

    // fc5 (fp32 path, N=200 ragged) -> regression output
    sgemm_nt<<<dim3((T_ + 127) / 128, B_ / 128, 4), 256>>>(r, fc5_w, part, B_, T_, R1_, R1_ / 4);
    reduce_bias_act<<<(B_ * T_ + 255) / 256, 256>>>(part, 4, B_ * T_, T_, fc5_b,
                                                    d_out + OUT_REG_OFF, 0);
}

// round 17
// speedup vs baseline: 1.3757x; 1.3757x over previous
#include <cuda_runtime.h>
#include <cuda_fp16.h>
#include <math.h>
#include <stdint.h>

// ---------------- problem constants ----------------
constexpr int B_  = 512;
constexpr int T_  = 200;
constexpr int D_  = 64;
constexpr int H_  = 256;
constexpr int BT  = B_ * T_;        // 102400 rows
constexpr int HT  = H_ * T_;        // 51200 flat dim
constexpr int C1_ = 1024;
constexpr int C2_ = 256;
constexpr int C3_ = 10;
constexpr int R1_ = 1024;
constexpr int G3  = 768;            // packed gates i,g,o (forget gate dead, c0=0)

constexpr size_t OUT_TOTAL_OFF = 0;
constexpr size_t OUT_CLASS_OFF = (size_t)BT * H_;
constexpr size_t OUT_REG_OFF   = OUT_CLASS_OFF + (size_t)B_ * C3_;

// ---------------- device scratch ----------------
__device__ __half g_w0h[G3 * D_];           // packed i,g,o rows fp16
__device__ __half g_w1h[G3 * H_];
__device__ float  g_bsel0[G3], g_bsel1[G3];
__device__ __half g_xh [(size_t)BT * D_];   // fp16 input
__device__ __half g_h0h[(size_t)BT * H_];   // fp16 h0
__device__ __half g_fh [(size_t)BT * H_];   // fp16 flat (out_total)
__device__ __half g_f1h[(size_t)C1_ * HT];  // fp16 fc1 weights
__device__ __half g_f4h[(size_t)R1_ * HT];  // fp16 fc4 weights
__device__ float  g_part[16 * 512 * 1024];  // split-K partials
__device__ float  g_c1[B_ * C1_];
__device__ float  g_c2[B_ * C2_];
__device__ float  g_r [B_ * R1_];

// ---------------- PTX helpers (sm_80-compatible only) ----------------
__device__ __forceinline__ uint32_t smem_u32(const void* p) {
    uint32_t a;
    asm("{ .reg .u64 t; cvta.to.shared.u64 t, %1; cvt.u32.u64 %0, t; }" : "=r"(a) : "l"(p));
    return a;
}
__device__ __forceinline__ void cp_async16(uint32_t dst, const void* src) {
    asm volatile("cp.async.cg.shared.global [%0], [%1], 16;" :: "r"(dst), "l"(src));
}
#define CP_COMMIT() asm volatile("cp.async.commit_group;" ::: "memory")
template <int N>
__device__ __forceinline__ void cp_wait() {
    asm volatile("cp.async.wait_group %0;" :: "n"(N) : "memory");
}
__device__ __forceinline__ void ldsm_x4(uint32_t* r, uint32_t addr) {
    asm volatile("ldmatrix.sync.aligned.m8n8.x4.shared.b16 {%0,%1,%2,%3}, [%4];"
                 : "=r"(r[0]), "=r"(r[1]), "=r"(r[2]), "=r"(r[3]) : "r"(addr));
}
__device__ __forceinline__ void mma_f16(float* c, const uint32_t* a, const uint32_t* b) {
    asm volatile("mma.sync.aligned.m16n8k16.row.col.f32.f16.f16.f32 "
                 "{%0,%1,%2,%3}, {%4,%5,%6,%7}, {%8,%9}, {%0,%1,%2,%3};"
                 : "+f"(c[0]), "+f"(c[1]), "+f"(c[2]), "+f"(c[3])
                 : "r"(a[0]), "r"(a[1]), "r"(a[2]), "r"(a[3]), "r"(b[0]), "r"(b[1]));
}
__device__ __forceinline__ uint32_t pack_h2(float a, float b) {
    __half2 t = __floats2half2_rn(a, b);
    return *reinterpret_cast<uint32_t*>(&t);
}
__device__ __forceinline__ float sigm(float x) { return 1.f / (1.f + expf(-x)); }

constexpr int HS_ROWB  = 144;               // 64 fp16 + 8 pad, bytes
constexpr int HS_TILE  = 128 * HS_ROWB;     // 18432
constexpr int HS_STAGE = 2 * HS_TILE;       // 36864 (A | B)  — fc kernel
constexpr int HS_SMEM  = 3 * HS_STAGE;      // 110592         — fc kernel

// gate kernel: stage = A | B0 | B1 (pass1 uses A | B only), double buffered
constexpr int G2_STAGE = 3 * HS_TILE;       // 55296
constexpr int G2_SMEM  = 2 * G2_STAGE;      // 110592

// ---------------- 2+1 fused gate fp16 GEMM (LSTM layers) ----------------
// Pass 1: acc_i, acc_g over K simultaneously -> stash = sigm(i+b)*tanh(g+b).
// Pass 2: acc_o over K -> h = sigm(o+b)*tanh(stash).
// Tile 128x128x64, 512 threads, warp grid 4x4, warp tile 32x32, 2-stage cp.async.
__global__ void __launch_bounds__(512, 1)
hs_gate2(const __half* __restrict__ A, const __half* __restrict__ Bw,
         float* __restrict__ C, const float* __restrict__ bias,
         __half* __restrict__ outH, int M, int K)
{
    extern __shared__ __align__(128) char smem[];
    const uint32_t sBase = smem_u32(smem);

    const int tid  = threadIdx.x;
    const int lane = tid & 31;
    const int warp = tid >> 5;
    const int wm   = warp >> 2;              // 0..3
    const int wn   = warp & 3;               // 0..3
    const int mBase = blockIdx.y * 128;
    const int nBase = blockIdx.x * 128;      // within H=256
    const int NC    = K >> 6;

    const int aRow  = (lane & 7) + ((lane >> 3) & 1) * 8;
    const int aCol  = (lane >> 4) * 8;
    const int bRow4 = ((lane >> 4) & 1) * 8 + (lane & 7);
    const int bColH = ((lane >> 3) & 1) * 8;

    const int lrow0 = tid >> 3;              // 0..63
    const int lrow1 = lrow0 + 64;
    const int lc8   = tid & 7;

    float stash[2][4][4];

    // ================= pass 1: gates i and g fused =================
    {
        float ai[2][4][4], ag[2][4][4];
#pragma unroll
        for (int mi = 0; mi < 2; mi++)
#pragma unroll
            for (int ni = 0; ni < 4; ni++)
#pragma unroll
                for (int q = 0; q < 4; q++) { ai[mi][ni][q] = 0.f; ag[mi][ni][q] = 0.f; }

        auto prefetch = [&](int c) {
            if (c < NC) {
                int kk = c * 64;
                uint32_t st = sBase + (c & 1) * G2_STAGE;
                cp_async16(st + lrow0 * HS_ROWB + lc8 * 16,
                           A + (size_t)(mBase + lrow0) * K + kk + lc8 * 8);
                cp_async16(st + lrow1 * HS_ROWB + lc8 * 16,
                           A + (size_t)(mBase + lrow1) * K + kk + lc8 * 8);
#pragma unroll
                for (int g = 0; g < 2; g++) {
                    int rowOff = g * 256 + nBase;
                    uint32_t bt = st + (g + 1) * HS_TILE;
                    cp_async16(bt + lrow0 * HS_ROWB + lc8 * 16,
                               Bw + (size_t)(rowOff + lrow0) * K + kk + lc8 * 8);
                    cp_async16(bt + lrow1 * HS_ROWB + lc8 * 16,
                               Bw + (size_t)(rowOff + lrow1) * K + kk + lc8 * 8);
                }
            }
            CP_COMMIT();
        };

        prefetch(0); prefetch(1);

        for (int c = 0; c < NC; c++) {
            cp_wait<1>();
            __syncthreads();

            uint32_t sA = sBase + (c & 1) * G2_STAGE;
#pragma unroll
            for (int ks = 0; ks < 4; ks++) {
                uint32_t ah[2][4], bi[2][4], bg[2][4];
#pragma unroll
                for (int mi = 0; mi < 2; mi++) {
                    uint32_t ro = (wm * 32 + mi * 16 + aRow) * HS_ROWB + (ks * 16 + aCol) * 2;
                    ldsm_x4(ah[mi], sA + ro);
                }
#pragma unroll
                for (int p = 0; p < 2; p++) {
                    uint32_t ro = (wn * 32 + p * 16 + bRow4) * HS_ROWB + (ks * 16 + bColH) * 2;
                    ldsm_x4(bi[p], sA + HS_TILE + ro);
                    ldsm_x4(bg[p], sA + 2 * HS_TILE + ro);
                }
#pragma unroll
                for (int mi = 0; mi < 2; mi++)
#pragma unroll
                    for (int ni = 0; ni < 4; ni++) {
                        mma_f16(ai[mi][ni], ah[mi], &bi[ni >> 1][(ni & 1) * 2]);
                        mma_f16(ag[mi][ni], ah[mi], &bg[ni >> 1][(ni & 1) * 2]);
                    }
            }
            __syncthreads();
            prefetch(c + 2);
        }

#pragma unroll
        for (int mi = 0; mi < 2; mi++)
#pragma unroll
            for (int ni = 0; ni < 4; ni++)
#pragma unroll
                for (int q = 0; q < 4; q++) {
                    int cl = wn * 32 + ni * 8 + (lane & 3) * 2 + (q & 1);
                    float vi = ai[mi][ni][q] + bias[nBase + cl];
                    float vg = ag[mi][ni][q] + bias[256 + nBase + cl];
                    stash[mi][ni][q] = sigm(vi) * tanhf(vg);
                }
    }

    // ================= pass 2: gate o =================
    {
        float ao[2][4][4];
#pragma unroll
        for (int mi = 0; mi < 2; mi++)
#pragma unroll
            for (int ni = 0; ni < 4; ni++)
#pragma unroll
                for (int q = 0; q < 4; q++) ao[mi][ni][q] = 0.f;

        const int rowOff = 512 + nBase;
        auto prefetch = [&](int c) {
            if (c < NC) {
                int kk = c * 64;
                uint32_t st = sBase + (c & 1) * G2_STAGE;
                cp_async16(st + lrow0 * HS_ROWB + lc8 * 16,
                           A + (size_t)(mBase + lrow0) * K + kk + lc8 * 8);
                cp_async16(st + lrow1 * HS_ROWB + lc8 * 16,
                           A + (size_t)(mBase + lrow1) * K + kk + lc8 * 8);
                cp_async16(st + HS_TILE + lrow0 * HS_ROWB + lc8 * 16,
                           Bw + (size_t)(rowOff + lrow0) * K + kk + lc8 * 8);
                cp_async16(st + HS_TILE + lrow1 * HS_ROWB + lc8 * 16,
                           Bw + (size_t)(rowOff + lrow1) * K + kk + lc8 * 8);
            }
            CP_COMMIT();
        };

        __syncthreads();                     // pass-1 MMAs done before refill
        prefetch(0); prefetch(1);

        for (int c = 0; c < NC; c++) {
            cp_wait<1>();
            __syncthreads();

            uint32_t sA = sBase + (c & 1) * G2_STAGE;
            uint32_t sB = sA + HS_TILE;
#pragma unroll
            for (int ks = 0; ks < 4; ks++) {
                uint32_t ah[2][4], bh[2][4];
#pragma unroll
                for (int mi = 0; mi < 2; mi++) {
                    uint32_t ro = (wm * 32 + mi * 16 + aRow) * HS_ROWB + (ks * 16 + aCol) * 2;
                    ldsm_x4(ah[mi], sA + ro);
                }
#pragma unroll
                for (int p = 0; p < 2; p++) {
                    uint32_t ro = (wn * 32 + p * 16 + bRow4) * HS_ROWB + (ks * 16 + bColH) * 2;
                    ldsm_x4(bh[p], sB + ro);
                }
#pragma unroll
                for (int mi = 0; mi < 2; mi++)
#pragma unroll
                    for (int ni = 0; ni < 4; ni++)
                        mma_f16(ao[mi][ni], ah[mi], &bh[ni >> 1][(ni & 1) * 2]);
            }
            __syncthreads();
            prefetch(c + 2);
        }

#pragma unroll
        for (int mi = 0; mi < 2; mi++)
#pragma unroll
            for (int ni = 0; ni < 4; ni++)
#pragma unroll
                for (int q = 0; q < 4; q++) {
                    int rl = wm * 32 + mi * 16 + (lane >> 2) + ((q >= 2) ? 8 : 0);
                    int cl = wn * 32 + ni * 8 + (lane & 3) * 2 + (q & 1);
                    float vo = ao[mi][ni][q] + bias[rowOff + cl];
                    float h = sigm(vo) * tanhf(stash[mi][ni][q]);
                    size_t o = (size_t)(mBase + rl) * H_ + nBase + cl;
                    if (C) C[o] = h;
                    outH[o] = __float2half(h);
                }
    }
}

// ---------------- fc fp16 GEMM: 64x32 warp tile, 2 CTAs/SM (R13 validated) ----------------
__global__ void __launch_bounds__(256, 2)
hs_fc(const __half* __restrict__ A, const __half* __restrict__ Bw,
      float* __restrict__ C, int M, int N, int K, int kSlice)
{
    extern __shared__ __align__(128) char smem[];
    const uint32_t sBase = smem_u32(smem);

    const int tid  = threadIdx.x;
    const int lane = tid & 31;
    const int warp = tid >> 5;               // 0..7
    const int wm   = warp >> 2;              // 0..1 (64 M-rows each)
    const int wn   = warp & 3;               // 0..3 (32 N-cols each)
    const int mBase = blockIdx.y * 128;
    const int nBase = blockIdx.x * 128;
    const int z     = blockIdx.z;
    const int kBeg  = z * kSlice;
    const int NC    = kSlice >> 6;

    const int aRow  = (lane & 7) + ((lane >> 3) & 1) * 8;
    const int aCol  = (lane >> 4) * 8;
    const int bRow4 = ((lane >> 4) & 1) * 8 + (lane & 7);
    const int bColH = ((lane >> 3) & 1) * 8;

    const int lc8 = tid & 7;
    int lrw[4];
#pragma unroll
    for (int t = 0; t < 4; t++) lrw[t] = (tid + t * 256) >> 3;   // 0..127

    float acc[4][4][4];
#pragma unroll
    for (int mi = 0; mi < 4; mi++)
#pragma unroll
        for (int ni = 0; ni < 4; ni++)
#pragma unroll
            for (int q = 0; q < 4; q++) acc[mi][ni][q] = 0.f;

    auto prefetch = [&](int c) {
        if (c < NC) {
            int kk = kBeg + c * 64;
            uint32_t st = sBase + (c % 3) * HS_STAGE;
#pragma unroll
            for (int t = 0; t < 4; t++) {
                cp_async16(st + lrw[t] * HS_ROWB + lc8 * 16,
                           A + (size_t)(mBase + lrw[t]) * K + kk + lc8 * 8);
                cp_async16(st + HS_TILE + lrw[t] * HS_ROWB + lc8 * 16,
                           Bw + (size_t)(nBase + lrw[t]) * K + kk + lc8 * 8);
            }
        }
        CP_COMMIT();
    };

    prefetch(0); prefetch(1); prefetch(2);

    for (int c = 0; c < NC; c++) {
        cp_wait<2>();
        __syncthreads();

        uint32_t sA = sBase + (c % 3) * HS_STAGE;
        uint32_t sB = sA + HS_TILE;
#pragma unroll
        for (int ks = 0; ks < 4; ks++) {
            uint32_t ah[4][4], bh[2][4];
#pragma unroll
            for (int mi = 0; mi < 4; mi++) {
                uint32_t ro = (wm * 64 + mi * 16 + aRow) * HS_ROWB + (ks * 16 + aCol) * 2;
                ldsm_x4(ah[mi], sA + ro);
            }
#pragma unroll
            for (int p = 0; p < 2; p++) {
                uint32_t ro = (wn * 32 + p * 16 + bRow4) * HS_ROWB + (ks * 16 + bColH) * 2;
                ldsm_x4(bh[p], sB + ro);
            }
#pragma unroll
            for (int mi = 0; mi < 4; mi++)
#pragma unroll
                for (int ni = 0; ni < 4; ni++)
                    mma_f16(acc[mi][ni], ah[mi], &bh[ni >> 1][(ni & 1) * 2]);
        }
        __syncthreads();
        prefetch(c + 3);
    }

    float* Cp = C + (size_t)z * M * N;
#pragma unroll
    for (int mi = 0; mi < 4; mi++) {
        int r0 = mBase + wm * 64 + mi * 16 + (lane >> 2);
#pragma unroll
        for (int ni = 0; ni < 4; ni++) {
            int col = nBase + wn * 32 + ni * 8 + (lane & 3) * 2;
            *reinterpret_cast<float2*>(&Cp[(size_t)r0 * N + col]) =
                make_float2(acc[mi][ni][0], acc[mi][ni][1]);
            *reinterpret_cast<float2*>(&Cp[(size_t)(r0 + 8) * N + col]) =
                make_float2(acc[mi][ni][2], acc[mi][ni][3]);
        }
    }
}

// ---------------- prep kernels ----------------
__global__ void cvt_f16(const float4* __restrict__ src, uint2* __restrict__ dst, int n4)
{
    int i = blockIdx.x * blockDim.x + threadIdx.x;
    if (i >= n4) return;
    float4 v = src[i];
    dst[i] = make_uint2(pack_h2(v.x, v.y), pack_h2(v.z, v.w));
}

__global__ void make_wsel_f16(const float* __restrict__ W, const float* __restrict__ bih,
                              const float* __restrict__ bhh, __half* __restrict__ Wh,
                              float* __restrict__ bsel, int Kd)
{
    int idx = blockIdx.x * blockDim.x + threadIdx.x;
    int total = G3 * Kd;
    if (idx < total) {
        int j = idx / Kd;
        int c = idx - j * Kd;
        int src = j + ((j >= 256) ? 256 : 0);
        Wh[idx] = __float2half(W[src * Kd + c]);
    }
    if (idx < G3) {
        int src = idx + ((idx >= 256) ? 256 : 0);
        bsel[idx] = bih[src] + bhh[src];
    }
}

__global__ void reduce_bias_act(const float* __restrict__ part, int S, int MN, int N,
                                const float* __restrict__ bias, float* __restrict__ out, int relu)
{
    int idx = blockIdx.x * blockDim.x + threadIdx.x;
    if (idx >= MN) return;
    float s = 0.f;
    for (int i = 0; i < S; i++) s += part[(size_t)i * MN + idx];
    s += bias[idx % N];
    if (relu) s = fmaxf(s, 0.f);
    out[idx] = s;
}

// ---------------- fp32 SGEMM (small fc layers) ----------------
__global__ void __launch_bounds__(256, 2)
sgemm_nt(const float* __restrict__ A, const float* __restrict__ B,
         float* __restrict__ C, int M, int N, int K, int kSlice)
{
    constexpr int BM = 128, BN = 128, BK = 8;
    __shared__ float As[BK][BM];
    __shared__ float Bs[BK][BN];
    const int tid = threadIdx.x;
    const int mBase = blockIdx.y * BM;
    const int nBase = blockIdx.x * BN;
    const int z = blockIdx.z;
    const int kBeg = z * kSlice;
    const int kEnd = kBeg + kSlice;
    const int lr = tid >> 1;
    const int lc = (tid & 1) * 4;
    const int tr = (tid >> 4) * 8;
    const int tc = (tid & 15) * 8;
    float acc[8][8];
#pragma unroll
    for (int i = 0; i < 8; i++)
#pragma unroll
        for (int j = 0; j < 8; j++) acc[i][j] = 0.f;
    const float* Aptr = A + (size_t)(mBase + lr) * K;
    const bool bvalid = (nBase + lr) < N;
    const float* Bptr = B + (bvalid ? (size_t)(nBase + lr) * K : 0);
    for (int k0 = kBeg; k0 < kEnd; k0 += BK) {
        float4 a4 = *reinterpret_cast<const float4*>(Aptr + k0 + lc);
        float4 b4 = make_float4(0.f, 0.f, 0.f, 0.f);
        if (bvalid) b4 = *reinterpret_cast<const float4*>(Bptr + k0 + lc);
        As[lc + 0][lr] = a4.x; As[lc + 1][lr] = a4.y;
        As[lc + 2][lr] = a4.z; As[lc + 3][lr] = a4.w;
        Bs[lc + 0][lr] = b4.x; Bs[lc + 1][lr] = b4.y;
        Bs[lc + 2][lr] = b4.z; Bs[lc + 3][lr] = b4.w;
        __syncthreads();
#pragma unroll
        for (int kk = 0; kk < BK; kk++) {
            float rm[8], rn[8];
#pragma unroll
            for (int i = 0; i < 8; i++) rm[i] = As[kk][tr + i];
#pragma unroll
            for (int j = 0; j < 8; j++) rn[j] = Bs[kk][tc + j];
#pragma unroll
            for (int i = 0; i < 8; i++)
#pragma unroll
                for (int j = 0; j < 8; j++) acc[i][j] = fmaf(rm[i], rn[j], acc[i][j]);
        }
        __syncthreads();
    }
    float* Cp = C + (size_t)z * M * N;
#pragma unroll
    for (int i = 0; i < 8; i++) {
        const size_t rowOff = (size_t)(mBase + tr + i) * N;
#pragma unroll
        for (int j = 0; j < 8; j++) {
            int col = nBase + tc + j;
            if (col < N) Cp[rowOff + col] = acc[i][j];
        }
    }
}

__global__ void fc3_kernel(const float* __restrict__ x, const float* __restrict__ W,
                           const float* __restrict__ b, float* __restrict__ out)
{
    int idx = blockIdx.x * blockDim.x + threadIdx.x;
    if (idx >= B_ * C3_) return;
    int m = idx / C3_;
    int n = idx - m * C3_;
    const float* xr = x + m * C2_;
    const float* wr = W + n * C2_;
    float s = 0.f;
#pragma unroll 4
    for (int k = 0; k < C2_; k++) s = fmaf(xr[k], wr[k], s);
    out[idx] = s + b[n];
}

// ---------------- launch ----------------
extern "C" void kernel_launch(void* const* d_in, const int* in_sizes, int n_in,
                              void* d_out_v, int out_size)
{
    const float* x     = (const float*)d_in[0];
    const float* W_ih0 = (const float*)d_in[1];
    const float* b_ih0 = (const float*)d_in[2];
    const float* b_hh0 = (const float*)d_in[3];
    const float* W_ih1 = (const float*)d_in[4];
    const float* b_ih1 = (const float*)d_in[5];
    const float* b_hh1 = (const float*)d_in[6];
    const float* fc1_w = (const float*)d_in[7];
    const float* fc1_b = (const float*)d_in[8];
    const float* fc2_w = (const float*)d_in[9];
    const float* fc2_b = (const float*)d_in[10];
    const float* fc3_w = (const float*)d_in[11];
    const float* fc3_b = (const float*)d_in[12];
    const float* fc4_w = (const float*)d_in[13];
    const float* fc4_b = (const float*)d_in[14];
    const float* fc5_w = (const float*)d_in[15];
    const float* fc5_b = (const float*)d_in[16];
    float* d_out = (float*)d_out_v;

    cudaFuncSetAttribute(hs_gate2, cudaFuncAttributeMaxDynamicSharedMemorySize, G2_SMEM);
    cudaFuncSetAttribute(hs_fc,    cudaFuncAttributeMaxDynamicSharedMemorySize, HS_SMEM);

    __half *w0h, *w1h, *xh, *h0h, *fh, *f1h, *f4h;
    float *bsel0, *bsel1, *part, *c1, *c2, *r;
    cudaGetSymbolAddress((void**)&w0h, g_w0h);
    cudaGetSymbolAddress((void**)&w1h, g_w1h);
    cudaGetSymbolAddress((void**)&bsel0, g_bsel0);
    cudaGetSymbolAddress((void**)&bsel1, g_bsel1);
    cudaGetSymbolAddress((void**)&xh,  g_xh);
    cudaGetSymbolAddress((void**)&h0h, g_h0h);
    cudaGetSymbolAddress((void**)&fh,  g_fh);
    cudaGetSymbolAddress((void**)&f1h, g_f1h);
    cudaGetSymbolAddress((void**)&f4h, g_f4h);
    cudaGetSymbolAddress((void**)&part, g_part);
    cudaGetSymbolAddress((void**)&c1, g_c1);
    cudaGetSymbolAddress((void**)&c2, g_c2);
    cudaGetSymbolAddress((void**)&r,  g_r);

    // prep: pack gate weights fp16 + convert x / fc weights to fp16 (one-time)
    make_wsel_f16<<<(G3 * D_ + 255) / 256, 256>>>(W_ih0, b_ih0, b_hh0, w0h, bsel0, D_);
    make_wsel_f16<<<(G3 * H_ + 255) / 256, 256>>>(W_ih1, b_ih1, b_hh1, w1h, bsel1, H_);
    cvt_f16<<<(BT * D_ / 4 + 255) / 256, 256>>>((const float4*)x, (uint2*)xh, BT * D_ / 4);
    cvt_f16<<<(C1_ * HT / 4 + 255) / 256, 256>>>((const float4*)fc1_w, (uint2*)f1h, C1_ * HT / 4);
    cvt_f16<<<(R1_ * HT / 4 + 255) / 256, 256>>>((const float4*)fc4_w, (uint2*)f4h, R1_ * HT / 4);

    // LSTM layer 0 (2+1 fused gates): h0 fp16 = lstm(x @ Wsel0^T + bsel0)
    hs_gate2<<<dim3(2, BT / 128, 1), 512, G2_SMEM>>>(
        xh, w0h, nullptr, bsel0, h0h, BT, D_);

    // LSTM layer 1 (2+1 fused gates): out_total fp32 -> d_out, flat fp16 -> fh
    hs_gate2<<<dim3(2, BT / 128, 1), 512, G2_SMEM>>>(
        h0h, w1h, d_out + OUT_TOTAL_OFF, bsel1, fh, BT, H_);

    // fc1 (split-K=16) + relu
    hs_fc<<<dim3(C1_ / 128, B_ / 128, 16), 256, HS_SMEM>>>(
        fh, f1h, part, B_, C1_, HT, HT / 16);
    reduce_bias_act<<<(B_ * C1_ + 255) / 256, 256>>>(part, 16, B_ * C1_, C1_, fc1_b, c1, 1);

    // fc2 (fp32 path) + relu
    sgemm_nt<<<dim3(C2_ / 128, B_ / 128, 4), 256>>>(c1, fc2_w, part, B_, C2_, C1_, C1_ / 4);
    reduce_bias_act<<<(B_ * C2_ + 255) / 256, 256>>>(part, 4, B_ * C2_, C2_, fc2_b, c2, 1);

    // fc3 -> class output
    fc3_kernel<<<(B_ * C3_ + 255) / 256, 256>>>(c2, fc3_w, fc3_b, d_out + OUT_CLASS_OFF);

    // fc4 (split-K=16) + relu
    hs_fc<<<dim3(R1_ / 128, B_ / 128, 16), 256, HS_SMEM>>>(
        fh, f4h, part, B_, R1_, HT, HT / 16);
    reduce_bias_act<<<(B_ * R1_ + 255) / 256, 256>>>(part, 16, B_ * R1_, R1_, fc4_b, r, 1);

    // fc5 (fp32 path, N=200 ragged) -> regression output
    sgemm_nt<<<dim3((T_ + 127) / 128, B_ / 128, 4), 256>>>(r, fc5_w, part, B_, T_, R1_, R1_ / 4);
    reduce_bias_act<<<(B_ * T_ + 255) / 256, 256>>>(part, 4, B_ * T_, T_, fc5_b,
                                                    d_out + OUT_REG_OFF, 0);
}